// round 2
// baseline (speedup 1.0000x reference)
#include <cuda_runtime.h>
#include <math.h>

#define N_TOK 16384
#define D_DIM 1024
#define E_EXP 8
#define H_DIM 4096
#define CAP   3072            // int(1.5 * 16384 / 8)
#define EC    (E_EXP * CAP)   // 24576

// ---------------- scratch (device globals; no allocations allowed) ----------
__device__ float g_h[(size_t)EC * H_DIM];     // 402 MB intermediate activations
__device__ int   g_tok[EC];                   // slot -> token id (N_TOK = pad)
__device__ float g_probs[N_TOK * E_EXP];
__device__ float g_gate[N_TOK];
__device__ int   g_gidx[N_TOK];

// ---------------- router: logits = x @ Wr + br, softmax, top-1 --------------
__global__ void router_kernel(const float* __restrict__ x,
                              const float* __restrict__ Wr,
                              const float* __restrict__ br) {
    int warp = (blockIdx.x * blockDim.x + threadIdx.x) >> 5;
    int lane = threadIdx.x & 31;
    if (warp >= N_TOK) return;
    const float* xr = x + (size_t)warp * D_DIM;

    float acc[E_EXP] = {0.f,0.f,0.f,0.f,0.f,0.f,0.f,0.f};
    #pragma unroll 8
    for (int j = 0; j < D_DIM / 32; j++) {
        float xv = xr[lane + 32 * j];
        const float4* w = (const float4*)(Wr + (size_t)(lane + 32 * j) * E_EXP);
        float4 w0 = w[0], w1 = w[1];
        acc[0] += xv * w0.x; acc[1] += xv * w0.y;
        acc[2] += xv * w0.z; acc[3] += xv * w0.w;
        acc[4] += xv * w1.x; acc[5] += xv * w1.y;
        acc[6] += xv * w1.z; acc[7] += xv * w1.w;
    }
    #pragma unroll
    for (int e = 0; e < E_EXP; e++)
        #pragma unroll
        for (int off = 16; off; off >>= 1)
            acc[e] += __shfl_down_sync(0xffffffffu, acc[e], off);

    if (lane == 0) {
        float l[E_EXP];
        float m = -1e30f; int idx = 0;
        #pragma unroll
        for (int e = 0; e < E_EXP; e++) {
            l[e] = acc[e] + br[e];
            if (l[e] > m) { m = l[e]; idx = e; }   // first-max, matches argmax
        }
        float p[E_EXP], s = 0.f;
        #pragma unroll
        for (int e = 0; e < E_EXP; e++) { p[e] = expf(l[e] - m); s += p[e]; }
        float inv = 1.f / s;
        #pragma unroll
        for (int e = 0; e < E_EXP; e++) g_probs[warp * E_EXP + e] = p[e] * inv;
        g_gate[warp] = p[idx] * inv;
        g_gidx[warp] = idx;
    }
}

// ---------------- dispatch: exact FIFO prefix positions, single block -------
__global__ void dispatch_kernel() {
    __shared__ int s[E_EXP][1024];
    int tid = threadIdx.x;

    // pad the whole slot table first (synced by first __syncthreads below)
    for (int i = tid; i < EC; i += 1024) g_tok[i] = N_TOK;

    int base = tid * 16;
    int ge[16];
    int lc[E_EXP] = {0,0,0,0,0,0,0,0};
    #pragma unroll
    for (int t = 0; t < 16; t++) { ge[t] = g_gidx[base + t]; lc[ge[t]]++; }
    #pragma unroll
    for (int e = 0; e < E_EXP; e++) s[e][tid] = lc[e];
    __syncthreads();

    // Hillis-Steele inclusive scan over 1024 chunks, all 8 experts at once
    for (int off = 1; off < 1024; off <<= 1) {
        int v[E_EXP];
        #pragma unroll
        for (int e = 0; e < E_EXP; e++) v[e] = (tid >= off) ? s[e][tid - off] : 0;
        __syncthreads();
        #pragma unroll
        for (int e = 0; e < E_EXP; e++) s[e][tid] += v[e];
        __syncthreads();
    }

    int pos[E_EXP];
    #pragma unroll
    for (int e = 0; e < E_EXP; e++) pos[e] = s[e][tid] - lc[e];  // exclusive

    #pragma unroll
    for (int t = 0; t < 16; t++) {
        int e = ge[t];
        int p = pos[e]++;
        if (p < CAP) g_tok[e * CAP + p] = base + t;   // FIFO; overflow dropped
    }
}

// ---------------- out = x * gate (pass-through for dropped tokens) ----------
__global__ void init_out_kernel(const float* __restrict__ x, float* __restrict__ out) {
    int i = blockIdx.x * blockDim.x + threadIdx.x;    // indexes float4
    float4 v = ((const float4*)x)[i];
    float g = g_gate[i >> 8];                          // 256 float4 per token row
    v.x *= g; v.y *= g; v.z *= g; v.w *= g;
    ((float4*)out)[i] = v;
}

// ---------------- GEMM1: h = silu(gather(x) @ W1 + b1)  [128x128x8 tiles] ---
__global__ __launch_bounds__(256) void gemm1_kernel(const float* __restrict__ x,
                                                    const float* __restrict__ W1,
                                                    const float* __restrict__ b1) {
    const int e    = blockIdx.z;
    const int row0 = blockIdx.y * 128;
    const int col0 = blockIdx.x * 128;
    const float* B = W1 + (size_t)e * D_DIM * H_DIM;

    __shared__ float As[8][132];
    __shared__ float Bs[8][128];
    __shared__ int   stok[128];

    int tid = threadIdx.x;
    if (tid < 128) stok[tid] = g_tok[e * CAP + row0 + tid];

    int tx = tid & 15, ty = tid >> 4;
    int arow = tid >> 1, ak4 = (tid & 1) * 4;
    int bk = tid >> 5,  bcol4 = (tid & 31) * 4;

    __syncthreads();
    int atok = stok[arow];
    const float* aptr = (atok < N_TOK) ? (x + (size_t)atok * D_DIM + ak4) : 0;
    const float* bptr = B + (size_t)bk * H_DIM + col0 + bcol4;

    float acc[8][8];
    #pragma unroll
    for (int i = 0; i < 8; i++)
        #pragma unroll
        for (int j = 0; j < 8; j++) acc[i][j] = 0.f;

    for (int kt = 0; kt < D_DIM; kt += 8) {
        float4 a = aptr ? *(const float4*)(aptr + kt) : make_float4(0.f,0.f,0.f,0.f);
        float4 b = *(const float4*)(bptr + (size_t)kt * H_DIM);
        __syncthreads();
        As[ak4 + 0][arow] = a.x; As[ak4 + 1][arow] = a.y;
        As[ak4 + 2][arow] = a.z; As[ak4 + 3][arow] = a.w;
        *(float4*)&Bs[bk][bcol4] = b;
        __syncthreads();
        #pragma unroll
        for (int kk = 0; kk < 8; kk++) {
            float ar[8], bc[8];
            *(float4*)(ar)     = *(const float4*)&As[kk][ty * 4];
            *(float4*)(ar + 4) = *(const float4*)&As[kk][64 + ty * 4];
            *(float4*)(bc)     = *(const float4*)&Bs[kk][tx * 4];
            *(float4*)(bc + 4) = *(const float4*)&Bs[kk][64 + tx * 4];
            #pragma unroll
            for (int i = 0; i < 8; i++)
                #pragma unroll
                for (int j = 0; j < 8; j++)
                    acc[i][j] += ar[i] * bc[j];
        }
    }

    const float* bias = b1 + (size_t)e * H_DIM;
    #pragma unroll
    for (int i = 0; i < 8; i++) {
        int r = row0 + ((i < 4) ? (ty * 4 + i) : (64 + ty * 4 + i - 4));
        float* hrow = g_h + (size_t)(e * CAP + r) * H_DIM;
        #pragma unroll
        for (int qj = 0; qj < 2; qj++) {
            int c = col0 + qj * 64 + tx * 4;
            float4 v;
            float t0 = acc[i][qj*4+0] + bias[c+0];
            float t1 = acc[i][qj*4+1] + bias[c+1];
            float t2 = acc[i][qj*4+2] + bias[c+2];
            float t3 = acc[i][qj*4+3] + bias[c+3];
            v.x = t0 / (1.f + expf(-t0));
            v.y = t1 / (1.f + expf(-t1));
            v.z = t2 / (1.f + expf(-t2));
            v.w = t3 / (1.f + expf(-t3));
            *(float4*)(hrow + c) = v;
        }
    }
}

// ---------------- GEMM2: out[token] = (h @ W2 + b2) * gate  (scatter) -------
__global__ __launch_bounds__(256) void gemm2_kernel(const float* __restrict__ W2,
                                                    const float* __restrict__ b2,
                                                    float* __restrict__ out) {
    const int e    = blockIdx.z;
    const int row0 = blockIdx.y * 128;
    const int col0 = blockIdx.x * 128;
    const float* A = g_h + (size_t)e * CAP * H_DIM;
    const float* B = W2 + (size_t)e * H_DIM * D_DIM;

    __shared__ float As[8][132];
    __shared__ float Bs[8][128];
    __shared__ int   stok[128];

    int tid = threadIdx.x;
    if (tid < 128) stok[tid] = g_tok[e * CAP + row0 + tid];

    int tx = tid & 15, ty = tid >> 4;
    int arow = tid >> 1, ak4 = (tid & 1) * 4;
    int bk = tid >> 5,  bcol4 = (tid & 31) * 4;

    const float* aptr = A + (size_t)(row0 + arow) * H_DIM + ak4;
    const float* bptr = B + (size_t)bk * D_DIM + col0 + bcol4;

    float acc[8][8];
    #pragma unroll
    for (int i = 0; i < 8; i++)
        #pragma unroll
        for (int j = 0; j < 8; j++) acc[i][j] = 0.f;

    __syncthreads();
    for (int kt = 0; kt < H_DIM; kt += 8) {
        float4 a = *(const float4*)(aptr + kt);
        float4 b = *(const float4*)(bptr + (size_t)kt * D_DIM);
        __syncthreads();
        As[ak4 + 0][arow] = a.x; As[ak4 + 1][arow] = a.y;
        As[ak4 + 2][arow] = a.z; As[ak4 + 3][arow] = a.w;
        *(float4*)&Bs[bk][bcol4] = b;
        __syncthreads();
        #pragma unroll
        for (int kk = 0; kk < 8; kk++) {
            float ar[8], bc[8];
            *(float4*)(ar)     = *(const float4*)&As[kk][ty * 4];
            *(float4*)(ar + 4) = *(const float4*)&As[kk][64 + ty * 4];
            *(float4*)(bc)     = *(const float4*)&Bs[kk][tx * 4];
            *(float4*)(bc + 4) = *(const float4*)&Bs[kk][64 + tx * 4];
            #pragma unroll
            for (int i = 0; i < 8; i++)
                #pragma unroll
                for (int j = 0; j < 8; j++)
                    acc[i][j] += ar[i] * bc[j];
        }
    }

    const float* bias = b2 + (size_t)e * D_DIM;
    #pragma unroll
    for (int i = 0; i < 8; i++) {
        int rloc = (i < 4) ? (ty * 4 + i) : (64 + ty * 4 + i - 4);
        int token = stok[rloc];
        if (token >= N_TOK) continue;           // pad slot: keep pass-through
        float g = g_gate[token];
        float* orow = out + (size_t)token * D_DIM;
        #pragma unroll
        for (int qj = 0; qj < 2; qj++) {
            int c = col0 + qj * 64 + tx * 4;
            float4 v;
            v.x = (acc[i][qj*4+0] + bias[c+0]) * g;
            v.y = (acc[i][qj*4+1] + bias[c+1]) * g;
            v.z = (acc[i][qj*4+2] + bias[c+2]) * g;
            v.w = (acc[i][qj*4+3] + bias[c+3]) * g;
            *(float4*)(orow + c) = v;
        }
    }
}

// ---------------- aux losses (deterministic fixed-order reduction) ----------
__global__ void loss_kernel(float* __restrict__ out, int out_size) {
    __shared__ float simp[E_EXP][256];
    __shared__ float sl1[256];
    int tid = threadIdx.x;
    float imp[E_EXP] = {0.f,0.f,0.f,0.f,0.f,0.f,0.f,0.f};
    float l1 = 0.f;
    for (int i = tid; i < N_TOK; i += 256) {
        #pragma unroll
        for (int e = 0; e < E_EXP; e++) {
            float p = g_probs[i * E_EXP + e];
            imp[e] += p; l1 += p;
        }
    }
    #pragma unroll
    for (int e = 0; e < E_EXP; e++) simp[e][tid] = imp[e];
    sl1[tid] = l1;
    __syncthreads();
    for (int off = 128; off; off >>= 1) {
        if (tid < off) {
            #pragma unroll
            for (int e = 0; e < E_EXP; e++) simp[e][tid] += simp[e][tid + off];
            sl1[tid] += sl1[tid + off];
        }
        __syncthreads();
    }
    if (tid == 0 && out_size >= N_TOK * D_DIM + 2) {
        float mean = 0.f;
        #pragma unroll
        for (int e = 0; e < E_EXP; e++) mean += simp[e][0];
        mean *= (1.f / E_EXP);
        float var = 0.f;
        #pragma unroll
        for (int e = 0; e < E_EXP; e++) {
            float d = simp[e][0] - mean; var += d * d;
        }
        var *= (1.f / E_EXP);
        out[N_TOK * D_DIM]     = sl1[0] / (float)N_TOK;   // l1_loss (== 1.0)
        out[N_TOK * D_DIM + 1] = var / (mean * mean);      // (std/mean)^2
    }
}

// ---------------- launch --------------------------------------------------
extern "C" void kernel_launch(void* const* d_in, const int* in_sizes, int n_in,
                              void* d_out, int out_size) {
    const float* x  = (const float*)d_in[0];
    const float* Wr = (const float*)d_in[1];
    const float* br = (const float*)d_in[2];
    const float* W1 = (const float*)d_in[3];
    const float* b1 = (const float*)d_in[4];
    const float* W2 = (const float*)d_in[5];
    const float* b2 = (const float*)d_in[6];
    float* out = (float*)d_out;

    router_kernel<<<N_TOK / 8, 256>>>(x, Wr, br);        // 8 warps/block
    dispatch_kernel<<<1, 1024>>>();
    init_out_kernel<<<(N_TOK * (D_DIM / 4)) / 256, 256>>>(x, out);

    dim3 g1(H_DIM / 128, CAP / 128, E_EXP);              // (32, 24, 8)
    gemm1_kernel<<<g1, 256>>>(x, W1, b1);

    dim3 g2(D_DIM / 128, CAP / 128, E_EXP);              // (8, 24, 8)
    gemm2_kernel<<<g2, 256>>>(W2, b2, out);

    loss_kernel<<<1, 256>>>(out, out_size);
}

// round 5
// speedup vs baseline: 2.3331x; 2.3331x over previous
#include <cuda_runtime.h>
#include <math.h>
#include <stdint.h>

#define N_TOK 16384
#define D_DIM 1024
#define E_EXP 8
#define H_DIM 4096
#define CAP   3072            // int(1.5 * 16384 / 8)
#define EC    (E_EXP * CAP)   // 24576

// GEMM tiling
#define BM 128
#define BN 256
#define BK 16
#define ROWP 20               // row stride in floats (BK + 4 pad) -> conflict-free frags
#define NSTG 3
#define NT 256

#define A_FLOATS (BM * ROWP)          // 2560
#define B_FLOATS (BN * ROWP)          // 5120
#define STG_FLOATS (A_FLOATS + B_FLOATS)   // 7680
#define SM_STOK_F (NSTG * STG_FLOATS)      // 23040 (floats)
#define SM_BIAS_F (SM_STOK_F + 128)
#define SMEM_TOTAL ((SM_BIAS_F + 256) * 4) // 93696 bytes

// ---------------- scratch ----------------------------------------------------
__device__ float g_h[(size_t)EC * H_DIM];                 // tf32-rounded activations
__device__ float g_xr[(size_t)N_TOK * D_DIM];             // rounded x
__device__ float g_W1t[(size_t)E_EXP * D_DIM * H_DIM];    // W1^T [e][H][D]
__device__ float g_W2t[(size_t)E_EXP * D_DIM * H_DIM];    // W2^T [e][D][H]
__device__ int   g_tok[EC];
__device__ float g_probs[N_TOK * E_EXP];
__device__ float g_gate[N_TOK];
__device__ int   g_gidx[N_TOK];

// ---------------- helpers ----------------------------------------------------
__device__ __forceinline__ uint32_t smem_u32(const void* p) {
    return (uint32_t)__cvta_generic_to_shared(p);
}
__device__ __forceinline__ float rna_tf32(float v) {
    float r;
    asm("cvt.rna.tf32.f32 %0, %1;" : "=f"(r) : "f"(v));
    return r;
}
__device__ __forceinline__ void cp16(uint32_t s, const void* g) {
    asm volatile("cp.async.cg.shared.global [%0], [%1], 16;" :: "r"(s), "l"(g));
}
__device__ __forceinline__ void mma_tf32(float* d, const uint32_t* a, const uint32_t* b) {
    asm volatile(
        "mma.sync.aligned.m16n8k8.row.col.f32.tf32.tf32.f32 "
        "{%0,%1,%2,%3}, {%4,%5,%6,%7}, {%8,%9}, {%0,%1,%2,%3};"
        : "+f"(d[0]), "+f"(d[1]), "+f"(d[2]), "+f"(d[3])
        : "r"(a[0]), "r"(a[1]), "r"(a[2]), "r"(a[3]), "r"(b[0]), "r"(b[1]));
}

// ---------------- pre-pass: round x to tf32 ----------------------------------
__global__ void round_x_kernel(const float4* __restrict__ src, float4* __restrict__ dst) {
    int i = blockIdx.x * blockDim.x + threadIdx.x;
    float4 v = src[i];
    v.x = rna_tf32(v.x); v.y = rna_tf32(v.y);
    v.z = rna_tf32(v.z); v.w = rna_tf32(v.w);
    dst[i] = v;
}

// ---------------- pre-pass: transpose W [e][R][C] -> [e][C][R] + round -------
__global__ void transpose_round_kernel(const float* __restrict__ src,
                                       float* __restrict__ dst, int R, int C) {
    __shared__ float t[32][33];
    int e = blockIdx.z;
    src += (size_t)e * R * C;
    dst += (size_t)e * R * C;
    int c0 = blockIdx.x * 32, r0 = blockIdx.y * 32;
    int tx = threadIdx.x, ty = threadIdx.y;   // 32 x 8
    #pragma unroll
    for (int j = 0; j < 4; j++)
        t[ty + 8 * j][tx] = src[(size_t)(r0 + ty + 8 * j) * C + c0 + tx];
    __syncthreads();
    #pragma unroll
    for (int j = 0; j < 4; j++)
        dst[(size_t)(c0 + ty + 8 * j) * R + r0 + tx] = rna_tf32(t[tx][ty + 8 * j]);
}

// ---------------- router -----------------------------------------------------
__global__ void router_kernel(const float* __restrict__ x,
                              const float* __restrict__ Wr,
                              const float* __restrict__ br) {
    int warp = (blockIdx.x * blockDim.x + threadIdx.x) >> 5;
    int lane = threadIdx.x & 31;
    if (warp >= N_TOK) return;
    const float* xr = x + (size_t)warp * D_DIM;

    float acc[E_EXP] = {0.f,0.f,0.f,0.f,0.f,0.f,0.f,0.f};
    #pragma unroll 8
    for (int j = 0; j < D_DIM / 32; j++) {
        float xv = xr[lane + 32 * j];
        const float4* w = (const float4*)(Wr + (size_t)(lane + 32 * j) * E_EXP);
        float4 w0 = w[0], w1 = w[1];
        acc[0] += xv * w0.x; acc[1] += xv * w0.y;
        acc[2] += xv * w0.z; acc[3] += xv * w0.w;
        acc[4] += xv * w1.x; acc[5] += xv * w1.y;
        acc[6] += xv * w1.z; acc[7] += xv * w1.w;
    }
    #pragma unroll
    for (int e = 0; e < E_EXP; e++)
        #pragma unroll
        for (int off = 16; off; off >>= 1)
            acc[e] += __shfl_down_sync(0xffffffffu, acc[e], off);

    if (lane == 0) {
        float l[E_EXP];
        float m = -1e30f; int idx = 0;
        #pragma unroll
        for (int e = 0; e < E_EXP; e++) {
            l[e] = acc[e] + br[e];
            if (l[e] > m) { m = l[e]; idx = e; }
        }
        float p[E_EXP], s = 0.f;
        #pragma unroll
        for (int e = 0; e < E_EXP; e++) { p[e] = expf(l[e] - m); s += p[e]; }
        float inv = 1.f / s;
        #pragma unroll
        for (int e = 0; e < E_EXP; e++) g_probs[warp * E_EXP + e] = p[e] * inv;
        g_gate[warp] = p[idx] * inv;
        g_gidx[warp] = idx;
    }
}

// ---------------- dispatch ---------------------------------------------------
__global__ void dispatch_kernel() {
    __shared__ int s[E_EXP][1024];
    int tid = threadIdx.x;
    for (int i = tid; i < EC; i += 1024) g_tok[i] = N_TOK;

    int base = tid * 16;
    int ge[16];
    int lc[E_EXP] = {0,0,0,0,0,0,0,0};
    #pragma unroll
    for (int t = 0; t < 16; t++) { ge[t] = g_gidx[base + t]; lc[ge[t]]++; }
    #pragma unroll
    for (int e = 0; e < E_EXP; e++) s[e][tid] = lc[e];
    __syncthreads();

    for (int off = 1; off < 1024; off <<= 1) {
        int v[E_EXP];
        #pragma unroll
        for (int e = 0; e < E_EXP; e++) v[e] = (tid >= off) ? s[e][tid - off] : 0;
        __syncthreads();
        #pragma unroll
        for (int e = 0; e < E_EXP; e++) s[e][tid] += v[e];
        __syncthreads();
    }

    int pos[E_EXP];
    #pragma unroll
    for (int e = 0; e < E_EXP; e++) pos[e] = s[e][tid] - lc[e];

    #pragma unroll
    for (int t = 0; t < 16; t++) {
        int e = ge[t];
        int p = pos[e]++;
        if (p < CAP) g_tok[e * CAP + p] = base + t;
    }
}

// ---------------- out = x * gate ---------------------------------------------
__global__ void init_out_kernel(const float* __restrict__ x, float* __restrict__ out) {
    int i = blockIdx.x * blockDim.x + threadIdx.x;
    float4 v = ((const float4*)x)[i];
    float g = g_gate[i >> 8];
    v.x *= g; v.y *= g; v.z *= g; v.w *= g;
    ((float4*)out)[i] = v;
}

// ---------------- tf32 mma.sync grouped GEMM ---------------------------------
// FIRST: g_h[slot] = rna(silu(gather(xr) @ W1t^T + b1))
// !FIRST: out[token] = (g_h @ W2t^T + b2) * gate  (scatter, skip pads)
template<int KDIM, int NDIM, bool FIRST>
__global__ __launch_bounds__(NT, 1) void moe_gemm(const float* __restrict__ Ag,
                                                  const float* __restrict__ Bg,
                                                  const float* __restrict__ biasg,
                                                  float* __restrict__ outg) {
    extern __shared__ float smem[];
    const int e    = blockIdx.z;
    const int row0 = blockIdx.y * BM;
    const int col0 = blockIdx.x * BN;
    const int tid  = threadIdx.x;
    const int warp = tid >> 5, lane = tid & 31;
    const int wm = (warp >> 2) * 64;       // warp grid 2 (M) x 4 (N)
    const int wn = (warp & 3) * 64;
    const int fr = lane >> 2, fc = lane & 3;
    const uint32_t sb = smem_u32(smem);

    int*   stok  = (int*)(smem + SM_STOK_F);
    float* sbias = smem + SM_BIAS_F;
    if (tid < BM) stok[tid] = g_tok[e * CAP + row0 + tid];
    if (tid < BN) sbias[tid] = biasg[(size_t)e * NDIM + col0 + tid];
    __syncthreads();

    const float* Be = Bg + (size_t)e * KDIM * NDIM + (size_t)col0 * KDIM;
    const float* Ae = FIRST ? Ag : (Ag + (size_t)(e * CAP + row0) * KDIM);

    const int NS = KDIM / BK;

    // ---- stage loader (cp.async into [rows][ROWP] padded layout) ----
    auto load_stage = [&](int kt, int buf) {
        const uint32_t abase = sb + buf * (STG_FLOATS * 4);
        const uint32_t bbase = abase + A_FLOATS * 4;
        const int k0 = kt * BK;
        #pragma unroll
        for (int i = 0; i < 2; i++) {                 // A: 128 rows x 4 seg16
            int lin = i * NT + tid;
            int r = lin >> 2, seg = lin & 3;
            const float* g;
            if (FIRST) {
                int t = stok[r]; t = (t < N_TOK) ? t : 0;
                g = Ag + (size_t)t * KDIM + k0 + seg * 4;
            } else {
                g = Ae + (size_t)r * KDIM + k0 + seg * 4;
            }
            cp16(abase + r * (ROWP * 4) + seg * 16, g);
        }
        #pragma unroll
        for (int i = 0; i < 4; i++) {                 // B: 256 rows x 4 seg16
            int lin = i * NT + tid;
            int r = lin >> 2, seg = lin & 3;
            cp16(bbase + r * (ROWP * 4) + seg * 16,
                 Be + (size_t)r * KDIM + k0 + seg * 4);
        }
        asm volatile("cp.async.commit_group;" ::: "memory");
    };

    float acc[4][8][4];
    #pragma unroll
    for (int mt = 0; mt < 4; mt++)
        #pragma unroll
        for (int nt = 0; nt < 8; nt++)
            #pragma unroll
            for (int q = 0; q < 4; q++) acc[mt][nt][q] = 0.f;

    load_stage(0, 0);
    load_stage(1, 1);

    for (int kt = 0; kt < NS; kt++) {
        const int buf = kt % NSTG;
        if (kt + 2 < NS) {
            load_stage(kt + 2, (kt + 2) % NSTG);
            asm volatile("cp.async.wait_group 2;" ::: "memory");
        } else if (kt + 1 < NS) {
            asm volatile("cp.async.wait_group 1;" ::: "memory");
        } else {
            asm volatile("cp.async.wait_group 0;" ::: "memory");
        }
        __syncthreads();

        const float* As = smem + buf * STG_FLOATS;
        const float* Bs = As + A_FLOATS;

        #pragma unroll
        for (int kk = 0; kk < 2; kk++) {
            const int kb = kk * 8;
            uint32_t af[4][4], bf[8][2];
            #pragma unroll
            for (int mt = 0; mt < 4; mt++) {
                const float* p = As + (wm + mt * 16 + fr) * ROWP + kb + fc;
                af[mt][0] = __float_as_uint(p[0]);
                af[mt][1] = __float_as_uint(p[8 * ROWP]);
                af[mt][2] = __float_as_uint(p[4]);
                af[mt][3] = __float_as_uint(p[8 * ROWP + 4]);
            }
            #pragma unroll
            for (int nt = 0; nt < 8; nt++) {
                const float* p = Bs + (wn + nt * 8 + fr) * ROWP + kb + fc;
                bf[nt][0] = __float_as_uint(p[0]);
                bf[nt][1] = __float_as_uint(p[4]);
            }
            #pragma unroll
            for (int mt = 0; mt < 4; mt++)
                #pragma unroll
                for (int nt = 0; nt < 8; nt++)
                    mma_tf32(acc[mt][nt], af[mt], bf[nt]);
        }
        __syncthreads();
    }

    // ---- epilogue ----
    #pragma unroll
    for (int mt = 0; mt < 4; mt++) {
        #pragma unroll
        for (int half = 0; half < 2; half++) {
            const int rl = wm + mt * 16 + fr + half * 8;
            if (FIRST) {
                float* hp = outg + (size_t)(e * CAP + row0 + rl) * NDIM + col0;
                #pragma unroll
                for (int nt = 0; nt < 8; nt++) {
                    int cc = wn + nt * 8 + 2 * fc;
                    float t0 = acc[mt][nt][half * 2 + 0] + sbias[cc];
                    float t1 = acc[mt][nt][half * 2 + 1] + sbias[cc + 1];
                    float2 v;
                    v.x = rna_tf32(t0 / (1.f + expf(-t0)));
                    v.y = rna_tf32(t1 / (1.f + expf(-t1)));
                    *(float2*)(hp + cc) = v;
                }
            } else {
                int tok = stok[rl];
                if (tok < N_TOK) {
                    float gv = g_gate[tok];
                    float* op = outg + (size_t)tok * NDIM + col0;
                    #pragma unroll
                    for (int nt = 0; nt < 8; nt++) {
                        int cc = wn + nt * 8 + 2 * fc;
                        float2 v;
                        v.x = (acc[mt][nt][half * 2 + 0] + sbias[cc]) * gv;
                        v.y = (acc[mt][nt][half * 2 + 1] + sbias[cc + 1]) * gv;
                        *(float2*)(op + cc) = v;
                    }
                }
            }
        }
    }
}

// ---------------- aux losses -------------------------------------------------
__global__ void loss_kernel(float* __restrict__ out, int out_size) {
    __shared__ float simp[E_EXP][256];
    __shared__ float sl1[256];
    int tid = threadIdx.x;
    float imp[E_EXP] = {0.f,0.f,0.f,0.f,0.f,0.f,0.f,0.f};
    float l1 = 0.f;
    for (int i = tid; i < N_TOK; i += 256) {
        #pragma unroll
        for (int e = 0; e < E_EXP; e++) {
            float p = g_probs[i * E_EXP + e];
            imp[e] += p; l1 += p;
        }
    }
    #pragma unroll
    for (int e = 0; e < E_EXP; e++) simp[e][tid] = imp[e];
    sl1[tid] = l1;
    __syncthreads();
    for (int off = 128; off; off >>= 1) {
        if (tid < off) {
            #pragma unroll
            for (int e = 0; e < E_EXP; e++) simp[e][tid] += simp[e][tid + off];
            sl1[tid] += sl1[tid + off];
        }
        __syncthreads();
    }
    if (tid == 0 && out_size >= N_TOK * D_DIM + 2) {
        float mean = 0.f;
        #pragma unroll
        for (int e = 0; e < E_EXP; e++) mean += simp[e][0];
        mean *= (1.f / E_EXP);
        float var = 0.f;
        #pragma unroll
        for (int e = 0; e < E_EXP; e++) {
            float d = simp[e][0] - mean; var += d * d;
        }
        var *= (1.f / E_EXP);
        out[N_TOK * D_DIM]     = sl1[0] / (float)N_TOK;
        out[N_TOK * D_DIM + 1] = var / (mean * mean);
    }
}

// ---------------- launch -----------------------------------------------------
extern "C" void kernel_launch(void* const* d_in, const int* in_sizes, int n_in,
                              void* d_out, int out_size) {
    const float* x  = (const float*)d_in[0];
    const float* Wr = (const float*)d_in[1];
    const float* br = (const float*)d_in[2];
    const float* W1 = (const float*)d_in[3];
    const float* b1 = (const float*)d_in[4];
    const float* W2 = (const float*)d_in[5];
    const float* b2 = (const float*)d_in[6];
    float* out = (float*)d_out;

    cudaFuncSetAttribute(moe_gemm<D_DIM, H_DIM, true>,
                         cudaFuncAttributeMaxDynamicSharedMemorySize, SMEM_TOTAL);
    cudaFuncSetAttribute(moe_gemm<H_DIM, D_DIM, false>,
                         cudaFuncAttributeMaxDynamicSharedMemorySize, SMEM_TOTAL);

    float* g_xr_p;   cudaGetSymbolAddress((void**)&g_xr_p,  g_xr);
    float* g_W1t_p;  cudaGetSymbolAddress((void**)&g_W1t_p, g_W1t);
    float* g_W2t_p;  cudaGetSymbolAddress((void**)&g_W2t_p, g_W2t);
    float* g_h_p;    cudaGetSymbolAddress((void**)&g_h_p,   g_h);

    round_x_kernel<<<(N_TOK * D_DIM / 4) / 256, 256>>>((const float4*)x, (float4*)g_xr_p);
    {
        dim3 g(H_DIM / 32, D_DIM / 32, E_EXP);
        transpose_round_kernel<<<g, dim3(32, 8)>>>(W1, g_W1t_p, D_DIM, H_DIM);
    }
    {
        dim3 g(D_DIM / 32, H_DIM / 32, E_EXP);
        transpose_round_kernel<<<g, dim3(32, 8)>>>(W2, g_W2t_p, H_DIM, D_DIM);
    }

    router_kernel<<<N_TOK / 8, 256>>>(x, Wr, br);
    dispatch_kernel<<<1, 1024>>>();
    init_out_kernel<<<(N_TOK * (D_DIM / 4)) / 256, 256>>>(x, out);

    {
        dim3 g(H_DIM / BN, CAP / BM, E_EXP);     // (16, 24, 8)
        moe_gemm<D_DIM, H_DIM, true><<<g, NT, SMEM_TOTAL>>>(g_xr_p, g_W1t_p, b1, g_h_p);
    }
    {
        dim3 g(D_DIM / BN, CAP / BM, E_EXP);     // (4, 24, 8)
        moe_gemm<H_DIM, D_DIM, false><<<g, NT, SMEM_TOTAL>>>(g_h_p, g_W2t_p, b2, out);
    }

    loss_kernel<<<1, 256>>>(out, out_size);
}

// round 6
// speedup vs baseline: 3.6317x; 1.5566x over previous
#include <cuda_runtime.h>
#include <math.h>
#include <stdint.h>

#define N_TOK 16384
#define D_DIM 1024
#define E_EXP 8
#define H_DIM 4096
#define CAP   3072            // int(1.5 * 16384 / 8)
#define EC    (E_EXP * CAP)   // 24576

// GEMM tiling
#define BM 128
#define BN 256
#define BK 16
#define ROWP 20               // row stride in floats (BK + 4 pad) -> conflict-free frags
#define NSTG 3
#define NT 256

#define A_FLOATS (BM * ROWP)          // 2560
#define B_FLOATS (BN * ROWP)          // 5120
#define STG_FLOATS (A_FLOATS + B_FLOATS)   // 7680
#define SM_STOK_F (NSTG * STG_FLOATS)      // 23040 (floats)
#define SM_BIAS_F (SM_STOK_F + 128)
#define SMEM_TOTAL ((SM_BIAS_F + 256) * 4) // 93696 bytes

// ---------------- scratch ----------------------------------------------------
__device__ float g_h[(size_t)EC * H_DIM];                 // tf32-rounded activations
__device__ float g_xr[(size_t)N_TOK * D_DIM];             // rounded x
__device__ float g_W1t[(size_t)E_EXP * D_DIM * H_DIM];    // W1^T [e][H][D]
__device__ float g_W2t[(size_t)E_EXP * D_DIM * H_DIM];    // W2^T [e][D][H]
__device__ int   g_tok[EC];
__device__ int   g_cnt[E_EXP];                            // real (<=CAP) rows per expert
__device__ float g_probs[N_TOK * E_EXP];
__device__ float g_gate[N_TOK];
__device__ int   g_gidx[N_TOK];

// ---------------- helpers ----------------------------------------------------
__device__ __forceinline__ uint32_t smem_u32(const void* p) {
    return (uint32_t)__cvta_generic_to_shared(p);
}
__device__ __forceinline__ float rna_tf32(float v) {
    float r;
    asm("cvt.rna.tf32.f32 %0, %1;" : "=f"(r) : "f"(v));
    return r;
}
__device__ __forceinline__ void cp16(uint32_t s, const void* g) {
    asm volatile("cp.async.cg.shared.global [%0], [%1], 16;" :: "r"(s), "l"(g));
}
__device__ __forceinline__ void mma_tf32(float* d, const uint32_t* a, const uint32_t* b) {
    asm volatile(
        "mma.sync.aligned.m16n8k8.row.col.f32.tf32.tf32.f32 "
        "{%0,%1,%2,%3}, {%4,%5,%6,%7}, {%8,%9}, {%0,%1,%2,%3};"
        : "+f"(d[0]), "+f"(d[1]), "+f"(d[2]), "+f"(d[3])
        : "r"(a[0]), "r"(a[1]), "r"(a[2]), "r"(a[3]), "r"(b[0]), "r"(b[1]));
}

// ---------------- pre-pass: round x to tf32 ----------------------------------
__global__ void round_x_kernel(const float4* __restrict__ src, float4* __restrict__ dst) {
    int i = blockIdx.x * blockDim.x + threadIdx.x;
    float4 v = src[i];
    v.x = rna_tf32(v.x); v.y = rna_tf32(v.y);
    v.z = rna_tf32(v.z); v.w = rna_tf32(v.w);
    dst[i] = v;
}

// ---------------- pre-pass: transpose W [e][R][C] -> [e][C][R] + round -------
__global__ void transpose_round_kernel(const float* __restrict__ src,
                                       float* __restrict__ dst, int R, int C) {
    __shared__ float t[32][33];
    int e = blockIdx.z;
    src += (size_t)e * R * C;
    dst += (size_t)e * R * C;
    int c0 = blockIdx.x * 32, r0 = blockIdx.y * 32;
    int tx = threadIdx.x, ty = threadIdx.y;   // 32 x 8
    #pragma unroll
    for (int j = 0; j < 4; j++)
        t[ty + 8 * j][tx] = src[(size_t)(r0 + ty + 8 * j) * C + c0 + tx];
    __syncthreads();
    #pragma unroll
    for (int j = 0; j < 4; j++)
        dst[(size_t)(c0 + ty + 8 * j) * R + r0 + tx] = rna_tf32(t[tx][ty + 8 * j]);
}

// ---------------- router -----------------------------------------------------
__global__ void router_kernel(const float* __restrict__ x,
                              const float* __restrict__ Wr,
                              const float* __restrict__ br) {
    int warp = (blockIdx.x * blockDim.x + threadIdx.x) >> 5;
    int lane = threadIdx.x & 31;
    if (warp >= N_TOK) return;
    const float* xr = x + (size_t)warp * D_DIM;

    float acc[E_EXP] = {0.f,0.f,0.f,0.f,0.f,0.f,0.f,0.f};
    #pragma unroll 8
    for (int j = 0; j < D_DIM / 32; j++) {
        float xv = xr[lane + 32 * j];
        const float4* w = (const float4*)(Wr + (size_t)(lane + 32 * j) * E_EXP);
        float4 w0 = w[0], w1 = w[1];
        acc[0] += xv * w0.x; acc[1] += xv * w0.y;
        acc[2] += xv * w0.z; acc[3] += xv * w0.w;
        acc[4] += xv * w1.x; acc[5] += xv * w1.y;
        acc[6] += xv * w1.z; acc[7] += xv * w1.w;
    }
    #pragma unroll
    for (int e = 0; e < E_EXP; e++)
        #pragma unroll
        for (int off = 16; off; off >>= 1)
            acc[e] += __shfl_down_sync(0xffffffffu, acc[e], off);

    if (lane == 0) {
        float l[E_EXP];
        float m = -1e30f; int idx = 0;
        #pragma unroll
        for (int e = 0; e < E_EXP; e++) {
            l[e] = acc[e] + br[e];
            if (l[e] > m) { m = l[e]; idx = e; }
        }
        float p[E_EXP], s = 0.f;
        #pragma unroll
        for (int e = 0; e < E_EXP; e++) { p[e] = expf(l[e] - m); s += p[e]; }
        float inv = 1.f / s;
        #pragma unroll
        for (int e = 0; e < E_EXP; e++) g_probs[warp * E_EXP + e] = p[e] * inv;
        g_gate[warp] = p[idx] * inv;
        g_gidx[warp] = idx;
    }
}

// ---------------- dispatch ---------------------------------------------------
__global__ void dispatch_kernel() {
    __shared__ int s[E_EXP][1024];
    int tid = threadIdx.x;
    for (int i = tid; i < EC; i += 1024) g_tok[i] = N_TOK;

    int base = tid * 16;
    int ge[16];
    int lc[E_EXP] = {0,0,0,0,0,0,0,0};
    #pragma unroll
    for (int t = 0; t < 16; t++) { ge[t] = g_gidx[base + t]; lc[ge[t]]++; }
    #pragma unroll
    for (int e = 0; e < E_EXP; e++) s[e][tid] = lc[e];
    __syncthreads();

    for (int off = 1; off < 1024; off <<= 1) {
        int v[E_EXP];
        #pragma unroll
        for (int e = 0; e < E_EXP; e++) v[e] = (tid >= off) ? s[e][tid - off] : 0;
        __syncthreads();
        #pragma unroll
        for (int e = 0; e < E_EXP; e++) s[e][tid] += v[e];
        __syncthreads();
    }

    if (tid == 1023) {
        #pragma unroll
        for (int e = 0; e < E_EXP; e++)
            g_cnt[e] = (s[e][1023] < CAP) ? s[e][1023] : CAP;
    }

    int pos[E_EXP];
    #pragma unroll
    for (int e = 0; e < E_EXP; e++) pos[e] = s[e][tid] - lc[e];

    #pragma unroll
    for (int t = 0; t < 16; t++) {
        int e = ge[t];
        int p = pos[e]++;
        if (p < CAP) g_tok[e * CAP + p] = base + t;
    }
}

// ---------------- out = x * gate ---------------------------------------------
__global__ void init_out_kernel(const float* __restrict__ x, float* __restrict__ out) {
    int i = blockIdx.x * blockDim.x + threadIdx.x;
    float4 v = ((const float4*)x)[i];
    float g = g_gate[i >> 8];
    v.x *= g; v.y *= g; v.z *= g; v.w *= g;
    ((float4*)out)[i] = v;
}

// ---------------- tf32 mma.sync grouped GEMM ---------------------------------
// FIRST: g_h[slot] = rna(silu(gather(xr) @ W1t^T + b1))
// !FIRST: out[token] = (g_h @ W2t^T + b2) * gate  (scatter, skip pads)
// Tiles whose whole 128-row slab is pad (row0 >= g_cnt[e]) exit immediately.
template<int KDIM, int NDIM, bool FIRST>
__global__ __launch_bounds__(NT, 1) void moe_gemm(const float* __restrict__ Ag,
                                                  const float* __restrict__ Bg,
                                                  const float* __restrict__ biasg,
                                                  float* __restrict__ outg) {
    extern __shared__ float smem[];
    const int e    = blockIdx.z;
    const int row0 = blockIdx.y * BM;
    if (row0 >= g_cnt[e]) return;            // all-pad tile: no work

    const int col0 = blockIdx.x * BN;
    const int tid  = threadIdx.x;
    const int warp = tid >> 5, lane = tid & 31;
    const int wm = (warp >> 2) * 64;         // warp grid 2 (M) x 4 (N)
    const int wn = (warp & 3) * 64;
    const int fr = lane >> 2, fc = lane & 3;
    const uint32_t sb = smem_u32(smem);

    int*   stok  = (int*)(smem + SM_STOK_F);
    float* sbias = smem + SM_BIAS_F;
    if (tid < BM) stok[tid] = g_tok[e * CAP + row0 + tid];
    if (tid < BN) sbias[tid] = biasg[(size_t)e * NDIM + col0 + tid];
    __syncthreads();

    const float* Be = Bg + (size_t)e * KDIM * NDIM + (size_t)col0 * KDIM;
    const float* Ae = FIRST ? Ag : (Ag + (size_t)(e * CAP + row0) * KDIM);

    const int NS = KDIM / BK;

    // ---- stage loader (cp.async into [rows][ROWP] padded layout) ----
    auto load_stage = [&](int kt, int buf) {
        const uint32_t abase = sb + buf * (STG_FLOATS * 4);
        const uint32_t bbase = abase + A_FLOATS * 4;
        const int k0 = kt * BK;
        #pragma unroll
        for (int i = 0; i < 2; i++) {                 // A: 128 rows x 4 seg16
            int lin = i * NT + tid;
            int r = lin >> 2, seg = lin & 3;
            const float* g;
            if (FIRST) {
                int t = stok[r]; t = (t < N_TOK) ? t : 0;
                g = Ag + (size_t)t * KDIM + k0 + seg * 4;
            } else {
                g = Ae + (size_t)r * KDIM + k0 + seg * 4;
            }
            cp16(abase + r * (ROWP * 4) + seg * 16, g);
        }
        #pragma unroll
        for (int i = 0; i < 4; i++) {                 // B: 256 rows x 4 seg16
            int lin = i * NT + tid;
            int r = lin >> 2, seg = lin & 3;
            cp16(bbase + r * (ROWP * 4) + seg * 16,
                 Be + (size_t)r * KDIM + k0 + seg * 4);
        }
        asm volatile("cp.async.commit_group;" ::: "memory");
    };

    float acc[4][8][4];
    #pragma unroll
    for (int mt = 0; mt < 4; mt++)
        #pragma unroll
        for (int nt = 0; nt < 8; nt++)
            #pragma unroll
            for (int q = 0; q < 4; q++) acc[mt][nt][q] = 0.f;

    load_stage(0, 0);
    load_stage(1, 1);

    for (int kt = 0; kt < NS; kt++) {
        const int buf = kt % NSTG;
        if (kt + 2 < NS) {
            load_stage(kt + 2, (kt + 2) % NSTG);
            asm volatile("cp.async.wait_group 2;" ::: "memory");
        } else if (kt + 1 < NS) {
            asm volatile("cp.async.wait_group 1;" ::: "memory");
        } else {
            asm volatile("cp.async.wait_group 0;" ::: "memory");
        }
        __syncthreads();

        const float* As = smem + buf * STG_FLOATS;
        const float* Bs = As + A_FLOATS;

        #pragma unroll
        for (int kk = 0; kk < 2; kk++) {
            const int kb = kk * 8;
            uint32_t af[4][4], bf[8][2];
            #pragma unroll
            for (int mt = 0; mt < 4; mt++) {
                const float* p = As + (wm + mt * 16 + fr) * ROWP + kb + fc;
                af[mt][0] = __float_as_uint(p[0]);
                af[mt][1] = __float_as_uint(p[8 * ROWP]);
                af[mt][2] = __float_as_uint(p[4]);
                af[mt][3] = __float_as_uint(p[8 * ROWP + 4]);
            }
            #pragma unroll
            for (int nt = 0; nt < 8; nt++) {
                const float* p = Bs + (wn + nt * 8 + fr) * ROWP + kb + fc;
                bf[nt][0] = __float_as_uint(p[0]);
                bf[nt][1] = __float_as_uint(p[4]);
            }
            #pragma unroll
            for (int mt = 0; mt < 4; mt++)
                #pragma unroll
                for (int nt = 0; nt < 8; nt++)
                    mma_tf32(acc[mt][nt], af[mt], bf[nt]);
        }
        __syncthreads();
    }

    // ---- epilogue ----
    #pragma unroll
    for (int mt = 0; mt < 4; mt++) {
        #pragma unroll
        for (int half = 0; half < 2; half++) {
            const int rl = wm + mt * 16 + fr + half * 8;
            if (FIRST) {
                float* hp = outg + (size_t)(e * CAP + row0 + rl) * NDIM + col0;
                #pragma unroll
                for (int nt = 0; nt < 8; nt++) {
                    int cc = wn + nt * 8 + 2 * fc;
                    float t0 = acc[mt][nt][half * 2 + 0] + sbias[cc];
                    float t1 = acc[mt][nt][half * 2 + 1] + sbias[cc + 1];
                    float2 v;
                    v.x = rna_tf32(t0 / (1.f + expf(-t0)));
                    v.y = rna_tf32(t1 / (1.f + expf(-t1)));
                    *(float2*)(hp + cc) = v;
                }
            } else {
                int tok = stok[rl];
                if (tok < N_TOK) {
                    float gv = g_gate[tok];
                    float* op = outg + (size_t)tok * NDIM + col0;
                    #pragma unroll
                    for (int nt = 0; nt < 8; nt++) {
                        int cc = wn + nt * 8 + 2 * fc;
                        float2 v;
                        v.x = (acc[mt][nt][half * 2 + 0] + sbias[cc]) * gv;
                        v.y = (acc[mt][nt][half * 2 + 1] + sbias[cc + 1]) * gv;
                        *(float2*)(op + cc) = v;
                    }
                }
            }
        }
    }
}

// ---------------- aux losses -------------------------------------------------
__global__ void loss_kernel(float* __restrict__ out, int out_size) {
    __shared__ float simp[E_EXP][256];
    __shared__ float sl1[256];
    int tid = threadIdx.x;
    float imp[E_EXP] = {0.f,0.f,0.f,0.f,0.f,0.f,0.f,0.f};
    float l1 = 0.f;
    for (int i = tid; i < N_TOK; i += 256) {
        #pragma unroll
        for (int e = 0; e < E_EXP; e++) {
            float p = g_probs[i * E_EXP + e];
            imp[e] += p; l1 += p;
        }
    }
    #pragma unroll
    for (int e = 0; e < E_EXP; e++) simp[e][tid] = imp[e];
    sl1[tid] = l1;
    __syncthreads();
    for (int off = 128; off; off >>= 1) {
        if (tid < off) {
            #pragma unroll
            for (int e = 0; e < E_EXP; e++) simp[e][tid] += simp[e][tid + off];
            sl1[tid] += sl1[tid + off];
        }
        __syncthreads();
    }
    if (tid == 0 && out_size >= N_TOK * D_DIM + 2) {
        float mean = 0.f;
        #pragma unroll
        for (int e = 0; e < E_EXP; e++) mean += simp[e][0];
        mean *= (1.f / E_EXP);
        float var = 0.f;
        #pragma unroll
        for (int e = 0; e < E_EXP; e++) {
            float d = simp[e][0] - mean; var += d * d;
        }
        var *= (1.f / E_EXP);
        out[N_TOK * D_DIM]     = sl1[0] / (float)N_TOK;
        out[N_TOK * D_DIM + 1] = var / (mean * mean);
    }
}

// ---------------- launch -----------------------------------------------------
extern "C" void kernel_launch(void* const* d_in, const int* in_sizes, int n_in,
                              void* d_out, int out_size) {
    const float* x  = (const float*)d_in[0];
    const float* Wr = (const float*)d_in[1];
    const float* br = (const float*)d_in[2];
    const float* W1 = (const float*)d_in[3];
    const float* b1 = (const float*)d_in[4];
    const float* W2 = (const float*)d_in[5];
    const float* b2 = (const float*)d_in[6];
    float* out = (float*)d_out;

    cudaFuncSetAttribute(moe_gemm<D_DIM, H_DIM, true>,
                         cudaFuncAttributeMaxDynamicSharedMemorySize, SMEM_TOTAL);
    cudaFuncSetAttribute(moe_gemm<H_DIM, D_DIM, false>,
                         cudaFuncAttributeMaxDynamicSharedMemorySize, SMEM_TOTAL);

    float* g_xr_p;   cudaGetSymbolAddress((void**)&g_xr_p,  g_xr);
    float* g_W1t_p;  cudaGetSymbolAddress((void**)&g_W1t_p, g_W1t);
    float* g_W2t_p;  cudaGetSymbolAddress((void**)&g_W2t_p, g_W2t);
    float* g_h_p;    cudaGetSymbolAddress((void**)&g_h_p,   g_h);

    round_x_kernel<<<(N_TOK * D_DIM / 4) / 256, 256>>>((const float4*)x, (float4*)g_xr_p);
    {
        dim3 g(H_DIM / 32, D_DIM / 32, E_EXP);
        transpose_round_kernel<<<g, dim3(32, 8)>>>(W1, g_W1t_p, D_DIM, H_DIM);
    }
    {
        dim3 g(D_DIM / 32, H_DIM / 32, E_EXP);
        transpose_round_kernel<<<g, dim3(32, 8)>>>(W2, g_W2t_p, H_DIM, D_DIM);
    }

    router_kernel<<<N_TOK / 8, 256>>>(x, Wr, br);
    dispatch_kernel<<<1, 1024>>>();
    init_out_kernel<<<(N_TOK * (D_DIM / 4)) / 256, 256>>>(x, out);

    {
        dim3 g(H_DIM / BN, CAP / BM, E_EXP);     // (16, 24, 8)
        moe_gemm<D_DIM, H_DIM, true><<<g, NT, SMEM_TOTAL>>>(g_xr_p, g_W1t_p, b1, g_h_p);
    }
    {
        dim3 g(D_DIM / BN, CAP / BM, E_EXP);     // (4, 24, 8)
        moe_gemm<H_DIM, D_DIM, false><<<g, NT, SMEM_TOTAL>>>(g_h_p, g_W2t_p, b2, out);
    }

    loss_kernel<<<1, 256>>>(out, out_size);
}

// round 7
// speedup vs baseline: 6.4081x; 1.7645x over previous
#include <cuda_runtime.h>
#include <cuda_fp16.h>
#include <math.h>
#include <stdint.h>

#define N_TOK 16384
#define D_DIM 1024
#define E_EXP 8
#define H_DIM 4096
#define CAP   3072            // int(1.5 * 16384 / 8)
#define EC    (E_EXP * CAP)   // 24576

// GEMM tiling (halves)
#define BM 128
#define BN 256
#define BK 32                 // k-halves per stage (2 x k16 MMA steps)
#define ROWP 40               // row stride in halves (BK + 8 pad) -> conflict-free
#define NSTG 3
#define NT 256

#define A_HALF (BM * ROWP)            // 5120
#define B_HALF (BN * ROWP)            // 10240
#define STG_HALF (A_HALF + B_HALF)    // 15360
#define SM_STOK_B (NSTG * STG_HALF * 2)   // 92160 bytes
#define SM_BIAS_B (SM_STOK_B + 512)
#define SMEM_TOTAL (SM_BIAS_B + 1024)     // 93696 bytes

// ---------------- scratch ----------------------------------------------------
__device__ __half g_h[(size_t)EC * H_DIM];                 // fp16 activations
__device__ __half g_xh[(size_t)N_TOK * D_DIM];             // fp16 x
__device__ __half g_W1t[(size_t)E_EXP * D_DIM * H_DIM];    // W1^T [e][H][D] fp16
__device__ __half g_W2t[(size_t)E_EXP * D_DIM * H_DIM];    // W2^T [e][D][H] fp16
__device__ int    g_tok[EC];
__device__ int    g_cnt[E_EXP];
__device__ float  g_probs[N_TOK * E_EXP];
__device__ float  g_gate[N_TOK];
__device__ int    g_gidx[N_TOK];

// ---------------- helpers ----------------------------------------------------
__device__ __forceinline__ uint32_t smem_u32(const void* p) {
    return (uint32_t)__cvta_generic_to_shared(p);
}
__device__ __forceinline__ void cp16(uint32_t s, const void* g) {
    asm volatile("cp.async.cg.shared.global [%0], [%1], 16;" :: "r"(s), "l"(g));
}
__device__ __forceinline__ void mma_f16(float* d, const uint32_t* a, const uint32_t* b) {
    asm volatile(
        "mma.sync.aligned.m16n8k16.row.col.f32.f16.f16.f32 "
        "{%0,%1,%2,%3}, {%4,%5,%6,%7}, {%8,%9}, {%0,%1,%2,%3};"
        : "+f"(d[0]), "+f"(d[1]), "+f"(d[2]), "+f"(d[3])
        : "r"(a[0]), "r"(a[1]), "r"(a[2]), "r"(a[3]), "r"(b[0]), "r"(b[1]));
}

// ---------------- pre-pass: x -> fp16 ----------------------------------------
__global__ void cvt_x_kernel(const float4* __restrict__ src, __half2* __restrict__ dst) {
    int i = blockIdx.x * blockDim.x + threadIdx.x;   // one float4 -> two half2
    float4 v = src[i];
    dst[2 * i]     = __floats2half2_rn(v.x, v.y);
    dst[2 * i + 1] = __floats2half2_rn(v.z, v.w);
}

// ---------------- pre-pass: transpose W [e][R][C] -> fp16 [e][C][R] ----------
__global__ void transpose_half_kernel(const float* __restrict__ src,
                                      __half* __restrict__ dst, int R, int C) {
    __shared__ float t[32][33];
    int e = blockIdx.z;
    src += (size_t)e * R * C;
    dst += (size_t)e * R * C;
    int c0 = blockIdx.x * 32, r0 = blockIdx.y * 32;
    int tx = threadIdx.x, ty = threadIdx.y;   // 32 x 8
    #pragma unroll
    for (int j = 0; j < 4; j++)
        t[ty + 8 * j][tx] = src[(size_t)(r0 + ty + 8 * j) * C + c0 + tx];
    __syncthreads();
    #pragma unroll
    for (int j = 0; j < 4; j++)
        dst[(size_t)(c0 + ty + 8 * j) * R + r0 + tx] = __float2half_rn(t[tx][ty + 8 * j]);
}

// ---------------- router -----------------------------------------------------
__global__ void router_kernel(const float* __restrict__ x,
                              const float* __restrict__ Wr,
                              const float* __restrict__ br) {
    int warp = (blockIdx.x * blockDim.x + threadIdx.x) >> 5;
    int lane = threadIdx.x & 31;
    if (warp >= N_TOK) return;
    const float* xr = x + (size_t)warp * D_DIM;

    float acc[E_EXP] = {0.f,0.f,0.f,0.f,0.f,0.f,0.f,0.f};
    #pragma unroll 8
    for (int j = 0; j < D_DIM / 32; j++) {
        float xv = xr[lane + 32 * j];
        const float4* w = (const float4*)(Wr + (size_t)(lane + 32 * j) * E_EXP);
        float4 w0 = w[0], w1 = w[1];
        acc[0] += xv * w0.x; acc[1] += xv * w0.y;
        acc[2] += xv * w0.z; acc[3] += xv * w0.w;
        acc[4] += xv * w1.x; acc[5] += xv * w1.y;
        acc[6] += xv * w1.z; acc[7] += xv * w1.w;
    }
    #pragma unroll
    for (int e = 0; e < E_EXP; e++)
        #pragma unroll
        for (int off = 16; off; off >>= 1)
            acc[e] += __shfl_down_sync(0xffffffffu, acc[e], off);

    if (lane == 0) {
        float l[E_EXP];
        float m = -1e30f; int idx = 0;
        #pragma unroll
        for (int e = 0; e < E_EXP; e++) {
            l[e] = acc[e] + br[e];
            if (l[e] > m) { m = l[e]; idx = e; }
        }
        float p[E_EXP], s = 0.f;
        #pragma unroll
        for (int e = 0; e < E_EXP; e++) { p[e] = expf(l[e] - m); s += p[e]; }
        float inv = 1.f / s;
        #pragma unroll
        for (int e = 0; e < E_EXP; e++) g_probs[warp * E_EXP + e] = p[e] * inv;
        g_gate[warp] = p[idx] * inv;
        g_gidx[warp] = idx;
    }
}

// ---------------- dispatch ---------------------------------------------------
__global__ void dispatch_kernel() {
    __shared__ int s[E_EXP][1024];
    int tid = threadIdx.x;
    for (int i = tid; i < EC; i += 1024) g_tok[i] = N_TOK;

    int base = tid * 16;
    int ge[16];
    int lc[E_EXP] = {0,0,0,0,0,0,0,0};
    #pragma unroll
    for (int t = 0; t < 16; t++) { ge[t] = g_gidx[base + t]; lc[ge[t]]++; }
    #pragma unroll
    for (int e = 0; e < E_EXP; e++) s[e][tid] = lc[e];
    __syncthreads();

    for (int off = 1; off < 1024; off <<= 1) {
        int v[E_EXP];
        #pragma unroll
        for (int e = 0; e < E_EXP; e++) v[e] = (tid >= off) ? s[e][tid - off] : 0;
        __syncthreads();
        #pragma unroll
        for (int e = 0; e < E_EXP; e++) s[e][tid] += v[e];
        __syncthreads();
    }

    if (tid == 1023) {
        #pragma unroll
        for (int e = 0; e < E_EXP; e++)
            g_cnt[e] = (s[e][1023] < CAP) ? s[e][1023] : CAP;
    }

    int pos[E_EXP];
    #pragma unroll
    for (int e = 0; e < E_EXP; e++) pos[e] = s[e][tid] - lc[e];

    #pragma unroll
    for (int t = 0; t < 16; t++) {
        int e = ge[t];
        int p = pos[e]++;
        if (p < CAP) g_tok[e * CAP + p] = base + t;
    }
}

// ---------------- out = x * gate ---------------------------------------------
__global__ void init_out_kernel(const float* __restrict__ x, float* __restrict__ out) {
    int i = blockIdx.x * blockDim.x + threadIdx.x;
    float4 v = ((const float4*)x)[i];
    float g = g_gate[i >> 8];
    v.x *= g; v.y *= g; v.z *= g; v.w *= g;
    ((float4*)out)[i] = v;
}

// ---------------- fp16 mma.sync grouped GEMM ---------------------------------
// FIRST: g_h[slot] = half(silu(gather(xh) @ W1t^T + b1))
// !FIRST: out[token] = (g_h @ W2t^T + b2) * gate  (scatter, skip pads)
template<int KDIM, int NDIM, bool FIRST>
__global__ __launch_bounds__(NT, 1) void moe_gemm(const __half* __restrict__ Ag,
                                                  const __half* __restrict__ Bg,
                                                  const float* __restrict__ biasg,
                                                  void* __restrict__ outg) {
    extern __shared__ char smem[];
    const int e    = blockIdx.z;
    const int row0 = blockIdx.y * BM;
    if (row0 >= g_cnt[e]) return;            // all-pad tile

    const int col0 = blockIdx.x * BN;
    const int tid  = threadIdx.x;
    const int warp = tid >> 5, lane = tid & 31;
    const int wm = (warp >> 2) * 64;         // warp grid 2 (M) x 4 (N)
    const int wn = (warp & 3) * 64;
    const int fr = lane >> 2, fc = lane & 3;
    const uint32_t sb = smem_u32(smem);

    int*   stok  = (int*)(smem + SM_STOK_B);
    float* sbias = (float*)(smem + SM_BIAS_B);
    if (tid < BM) stok[tid] = g_tok[e * CAP + row0 + tid];
    if (tid < BN) sbias[tid] = biasg[(size_t)e * NDIM + col0 + tid];
    __syncthreads();

    const __half* Be = Bg + (size_t)e * KDIM * NDIM + (size_t)col0 * KDIM;
    const __half* Ae = FIRST ? Ag : (Ag + (size_t)(e * CAP + row0) * KDIM);

    const int NS = KDIM / BK;

    // ---- stage loader: rows of BK=32 halves (64B = 4 x cp16) ----
    auto load_stage = [&](int kt, int buf) {
        const uint32_t abase = sb + buf * (STG_HALF * 2);
        const uint32_t bbase = abase + A_HALF * 2;
        const int k0 = kt * BK;
        #pragma unroll
        for (int i = 0; i < 2; i++) {                 // A: 128 rows x 4 seg16
            int lin = i * NT + tid;
            int r = lin >> 2, seg = lin & 3;
            const __half* g;
            if (FIRST) {
                int t = stok[r]; t = (t < N_TOK) ? t : 0;
                g = Ag + (size_t)t * KDIM + k0 + seg * 8;
            } else {
                g = Ae + (size_t)r * KDIM + k0 + seg * 8;
            }
            cp16(abase + r * (ROWP * 2) + seg * 16, g);
        }
        #pragma unroll
        for (int i = 0; i < 4; i++) {                 // B: 256 rows x 4 seg16
            int lin = i * NT + tid;
            int r = lin >> 2, seg = lin & 3;
            cp16(bbase + r * (ROWP * 2) + seg * 16,
                 Be + (size_t)r * KDIM + k0 + seg * 8);
        }
        asm volatile("cp.async.commit_group;" ::: "memory");
    };

    float acc[4][8][4];
    #pragma unroll
    for (int mt = 0; mt < 4; mt++)
        #pragma unroll
        for (int nt = 0; nt < 8; nt++)
            #pragma unroll
            for (int q = 0; q < 4; q++) acc[mt][nt][q] = 0.f;

    load_stage(0, 0);
    load_stage(1, 1);

    for (int kt = 0; kt < NS; kt++) {
        const int buf = kt % NSTG;
        if (kt + 2 < NS) {
            load_stage(kt + 2, (kt + 2) % NSTG);
            asm volatile("cp.async.wait_group 2;" ::: "memory");
        } else if (kt + 1 < NS) {
            asm volatile("cp.async.wait_group 1;" ::: "memory");
        } else {
            asm volatile("cp.async.wait_group 0;" ::: "memory");
        }
        __syncthreads();

        const uint32_t* Asw = (const uint32_t*)(smem + buf * (STG_HALF * 2));
        const uint32_t* Bsw = Asw + A_HALF / 2;       // word (half2) indexing

        #pragma unroll
        for (int kk = 0; kk < 2; kk++) {
            const int kw = kk * 8;                    // k16 step in words
            uint32_t af[4][4], bf[8][2];
            #pragma unroll
            for (int mt = 0; mt < 4; mt++) {
                int base = (wm + mt * 16 + fr) * (ROWP / 2) + kw + fc;
                af[mt][0] = Asw[base];
                af[mt][1] = Asw[base + 8 * (ROWP / 2)];
                af[mt][2] = Asw[base + 4];
                af[mt][3] = Asw[base + 8 * (ROWP / 2) + 4];
            }
            #pragma unroll
            for (int nt = 0; nt < 8; nt++) {
                int nb = (wn + nt * 8 + fr) * (ROWP / 2) + kw + fc;
                bf[nt][0] = Bsw[nb];
                bf[nt][1] = Bsw[nb + 4];
            }
            #pragma unroll
            for (int mt = 0; mt < 4; mt++)
                #pragma unroll
                for (int nt = 0; nt < 8; nt++)
                    mma_f16(acc[mt][nt], af[mt], bf[nt]);
        }
        __syncthreads();
    }

    // ---- epilogue ----
    #pragma unroll
    for (int mt = 0; mt < 4; mt++) {
        #pragma unroll
        for (int half = 0; half < 2; half++) {
            const int rl = wm + mt * 16 + fr + half * 8;
            if (FIRST) {
                __half* hp = (__half*)outg + (size_t)(e * CAP + row0 + rl) * NDIM + col0;
                #pragma unroll
                for (int nt = 0; nt < 8; nt++) {
                    int cc = wn + nt * 8 + 2 * fc;
                    float t0 = acc[mt][nt][half * 2 + 0] + sbias[cc];
                    float t1 = acc[mt][nt][half * 2 + 1] + sbias[cc + 1];
                    *(__half2*)(hp + cc) =
                        __floats2half2_rn(t0 / (1.f + expf(-t0)),
                                          t1 / (1.f + expf(-t1)));
                }
            } else {
                int tok = stok[rl];
                if (tok < N_TOK) {
                    float gv = g_gate[tok];
                    float* op = (float*)outg + (size_t)tok * NDIM + col0;
                    #pragma unroll
                    for (int nt = 0; nt < 8; nt++) {
                        int cc = wn + nt * 8 + 2 * fc;
                        float2 v;
                        v.x = (acc[mt][nt][half * 2 + 0] + sbias[cc]) * gv;
                        v.y = (acc[mt][nt][half * 2 + 1] + sbias[cc + 1]) * gv;
                        *(float2*)(op + cc) = v;
                    }
                }
            }
        }
    }
}

// ---------------- aux losses -------------------------------------------------
__global__ void loss_kernel(float* __restrict__ out, int out_size) {
    __shared__ float simp[E_EXP][256];
    __shared__ float sl1[256];
    int tid = threadIdx.x;
    float imp[E_EXP] = {0.f,0.f,0.f,0.f,0.f,0.f,0.f,0.f};
    float l1 = 0.f;
    for (int i = tid; i < N_TOK; i += 256) {
        #pragma unroll
        for (int e = 0; e < E_EXP; e++) {
            float p = g_probs[i * E_EXP + e];
            imp[e] += p; l1 += p;
        }
    }
    #pragma unroll
    for (int e = 0; e < E_EXP; e++) simp[e][tid] = imp[e];
    sl1[tid] = l1;
    __syncthreads();
    for (int off = 128; off; off >>= 1) {
        if (tid < off) {
            #pragma unroll
            for (int e = 0; e < E_EXP; e++) simp[e][tid] += simp[e][tid + off];
            sl1[tid] += sl1[tid + off];
        }
        __syncthreads();
    }
    if (tid == 0 && out_size >= N_TOK * D_DIM + 2) {
        float mean = 0.f;
        #pragma unroll
        for (int e = 0; e < E_EXP; e++) mean += simp[e][0];
        mean *= (1.f / E_EXP);
        float var = 0.f;
        #pragma unroll
        for (int e = 0; e < E_EXP; e++) {
            float d = simp[e][0] - mean; var += d * d;
        }
        var *= (1.f / E_EXP);
        out[N_TOK * D_DIM]     = sl1[0] / (float)N_TOK;
        out[N_TOK * D_DIM + 1] = var / (mean * mean);
    }
}

// ---------------- launch -----------------------------------------------------
extern "C" void kernel_launch(void* const* d_in, const int* in_sizes, int n_in,
                              void* d_out, int out_size) {
    const float* x  = (const float*)d_in[0];
    const float* Wr = (const float*)d_in[1];
    const float* br = (const float*)d_in[2];
    const float* W1 = (const float*)d_in[3];
    const float* b1 = (const float*)d_in[4];
    const float* W2 = (const float*)d_in[5];
    const float* b2 = (const float*)d_in[6];
    float* out = (float*)d_out;

    cudaFuncSetAttribute(moe_gemm<D_DIM, H_DIM, true>,
                         cudaFuncAttributeMaxDynamicSharedMemorySize, SMEM_TOTAL);
    cudaFuncSetAttribute(moe_gemm<H_DIM, D_DIM, false>,
                         cudaFuncAttributeMaxDynamicSharedMemorySize, SMEM_TOTAL);

    __half* g_xh_p;  cudaGetSymbolAddress((void**)&g_xh_p,  g_xh);
    __half* g_W1t_p; cudaGetSymbolAddress((void**)&g_W1t_p, g_W1t);
    __half* g_W2t_p; cudaGetSymbolAddress((void**)&g_W2t_p, g_W2t);
    __half* g_h_p;   cudaGetSymbolAddress((void**)&g_h_p,   g_h);

    cvt_x_kernel<<<(N_TOK * D_DIM / 4) / 256, 256>>>((const float4*)x, (__half2*)g_xh_p);
    {
        dim3 g(H_DIM / 32, D_DIM / 32, E_EXP);
        transpose_half_kernel<<<g, dim3(32, 8)>>>(W1, g_W1t_p, D_DIM, H_DIM);
    }
    {
        dim3 g(D_DIM / 32, H_DIM / 32, E_EXP);
        transpose_half_kernel<<<g, dim3(32, 8)>>>(W2, g_W2t_p, H_DIM, D_DIM);
    }

    router_kernel<<<N_TOK / 8, 256>>>(x, Wr, br);
    dispatch_kernel<<<1, 1024>>>();
    init_out_kernel<<<(N_TOK * (D_DIM / 4)) / 256, 256>>>(x, out);

    {
        dim3 g(H_DIM / BN, CAP / BM, E_EXP);     // (16, 24, 8)
        moe_gemm<D_DIM, H_DIM, true><<<g, NT, SMEM_TOTAL>>>(g_xh_p, g_W1t_p, b1, g_h_p);
    }
    {
        dim3 g(D_DIM / BN, CAP / BM, E_EXP);     // (4, 24, 8)
        moe_gemm<H_DIM, D_DIM, false><<<g, NT, SMEM_TOTAL>>>(g_h_p, g_W2t_p, b2, out);
    }

    loss_kernel<<<1, 256>>>(out, out_size);
}